// round 16
// baseline (speedup 1.0000x reference)
#include <cuda_runtime.h>
#include <cuda_bf16.h>
#include <cstdint>
#include <cstddef>

// Problem dims
#define BB   128
#define TT   512
#define EE   256
#define UU   512
#define ZZ   2048          // 4*U
#define NCU  64            // u-groups (8 units each)
#define UT   8             // units per CTA group
#define CPC  32            // z-cols per CTA (4 gates * 8 units)
#define NCTA 128           // persistent grid

typedef __nv_bfloat16 bf16;

// ---------------- scratch (device globals; no allocations) ----------------
__device__ __align__(16) bf16  g_emb16[32000 * EE];          // bf16 embedding (16.4 MB)
__device__ __align__(16) bf16  g_WxGt [NCU * CPC * EE];      // gathered Wx, [cu][jp][k] (1 MB)
__device__ __align__(16) bf16  g_WhGt [NCU * CPC * UU];      // gathered Wh, [cu][jp][k] (2 MB)
__device__ __align__(16) float g_bG   [ZZ];                  // gathered bias
__device__ __align__(1024) bf16 g_hbuf[2 * BB * UU];         // h double buffer
__device__ __align__(16) unsigned g_flags[NCTA * 32];        // per-CTA epoch flags, 128B padded

// gather map: gc -> original column
__device__ __forceinline__ int orig_col(int gc) {
    int cu   = gc >> 5;
    int gate = (gc >> 3) & 3;
    int j    = gc & 7;
    return gate * UU + cu * UT + j;
}

__device__ __forceinline__ float tanh_apx(float x) {
    float y;
    asm("tanh.approx.f32 %0, %1;" : "=f"(y) : "f"(x));
    return y;
}
__device__ __forceinline__ float sigm_apx(float x) {
    return fmaf(tanh_apx(0.5f * x), 0.5f, 0.5f);
}

__device__ __forceinline__ void mma_bf16(float& d0, float& d1, float& d2, float& d3,
                                         uint32_t a0, uint32_t a1, uint32_t a2, uint32_t a3,
                                         uint32_t b0, uint32_t b1) {
    asm volatile(
        "mma.sync.aligned.m16n8k16.row.col.f32.bf16.bf16.f32 "
        "{%0,%1,%2,%3}, {%4,%5,%6,%7}, {%8,%9}, {%0,%1,%2,%3};"
        : "+f"(d0), "+f"(d1), "+f"(d2), "+f"(d3)
        : "r"(a0), "r"(a1), "r"(a2), "r"(a3), "r"(b0), "r"(b1));
}

__device__ __forceinline__ void ldsm_x4(uint32_t& r0, uint32_t& r1, uint32_t& r2, uint32_t& r3,
                                        uint32_t addr) {
    asm volatile("ldmatrix.sync.aligned.m8n8.x4.shared.b16 {%0,%1,%2,%3}, [%4];"
                 : "=r"(r0), "=r"(r1), "=r"(r2), "=r"(r3) : "r"(addr));
}

__device__ __forceinline__ void cp_async16(uint32_t dst_smem, const void* src) {
    asm volatile("cp.async.cg.shared.global [%0], [%1], 16;" :: "r"(dst_smem), "l"(src));
}

// ---------------- init kernels ----------------
__global__ void k_cvt_emb(const float* __restrict__ src) {
    int n4 = 32000 * EE / 4;
    for (int i = blockIdx.x * blockDim.x + threadIdx.x; i < n4; i += gridDim.x * blockDim.x) {
        float4 v = *(const float4*)(src + (size_t)i * 4);
        bf16* d = g_emb16 + (size_t)i * 4;
        d[0] = __float2bfloat16(v.x);
        d[1] = __float2bfloat16(v.y);
        d[2] = __float2bfloat16(v.z);
        d[3] = __float2bfloat16(v.w);
    }
}

// gather Wx into [cu][jp][k] (32 rows x 256 K per u-group), like Wh
__global__ void k_gather_wx(const float* __restrict__ Wx, const float* __restrict__ bvec) {
    int n = NCU * CPC * EE;
    for (int i = blockIdx.x * blockDim.x + threadIdx.x; i < n; i += gridDim.x * blockDim.x) {
        int cu = i >> 13;             // / (32*256)
        int jp = (i >> 8) & 31;
        int k  = i & 255;
        int gate = jp >> 3;
        int j    = jp & 7;
        g_WxGt[i] = __float2bfloat16(Wx[(size_t)k * ZZ + gate * UU + cu * UT + j]);
    }
    int t = blockIdx.x * blockDim.x + threadIdx.x;
    if (t < ZZ) g_bG[t] = bvec[orig_col(t)];
}

__global__ void k_gather_wh(const float* __restrict__ Wh) {
    int n = NCU * CPC * UU;
    for (int i = blockIdx.x * blockDim.x + threadIdx.x; i < n; i += gridDim.x * blockDim.x) {
        int cu = i >> 14;             // / (32*512)
        int jp = (i >> 9) & 31;
        int k  = i & 511;
        int gate = jp >> 3;
        int j    = jp & 7;
        g_WhGt[i] = __float2bfloat16(Wh[(size_t)k * ZZ + gate * UU + cu * UT + j]);
    }
}

__global__ void k_zero_state() {
    int tid = blockIdx.x * blockDim.x + threadIdx.x;
    int n = BB * UU;
    for (int i = tid; i < n; i += gridDim.x * blockDim.x)
        g_hbuf[i] = __float2bfloat16(0.0f);     // buffer 0 (read by step 0)
    for (int i = tid; i < NCTA * 32; i += gridDim.x * blockDim.x)
        g_flags[i] = 0u;
}

// ---------------- fused persistent recurrence, 2-way K-split, private staging ----------------
// 128 CTAs x 256 threads (8 warps). cu = bx&63, mg = bx>>6.
// Warp (mw = warp&3, kw2 = warp>>2): A-rows [m0+16mw,+16), K-half [256*kw2,+256) of h.
// Private staging per warp (own cp.async FIFO). kw2=1 partials via sred; kw2=0 owns gates.
// R16: publish barrier covers only warps 0-3 (bar.sync 1,128) so kw2=1 warps run ahead
// into the next step's x-GEMM; flag poll uses a relaxed preload hidden under the x-GEMM
// with fence.acq_rel fast path.
// dyn smem layout (bytes):
//   Bs  (Wh 32x520)        @ 0       33280
//   hs  (h tile 64x520)    @ 33280   66560
//   Wxs (Wx 32x264)        @ 99840   16896
//   Es  (emb 2 x 64x264)   @ 116736  67584
//   sred(64 x 32 f32)      @ 184320  8192
//   tks (int 64)           @ 192512  256     -> total 192768
__global__ __launch_bounds__(256) void k_recur(const int* __restrict__ sentence) {
    extern __shared__ __align__(128) char dsm[];
    bf16*  Bs   = (bf16*)dsm;
    bf16*  Wxs  = (bf16*)(dsm + 99840);
    float* sred = (float*)(dsm + 184320);
    int*   tks  = (int*) (dsm + 192512);

    uint32_t base_u32 = (uint32_t)__cvta_generic_to_shared(dsm);
    uint32_t Bs_u32   = base_u32;
    uint32_t hs_u32   = base_u32 + 33280;
    uint32_t Wxs_u32  = base_u32 + 99840;
    uint32_t Es_u32   = base_u32 + 116736;

    int tid  = threadIdx.x;
    int warp = tid >> 5;
    int lane = tid & 31;
    int tg   = lane & 3;
    int gid  = lane >> 2;

    int mw  = warp & 3;
    int kw2 = warp >> 2;
    int wm  = mw * 16;

    int cu = blockIdx.x & 63;
    int mg = blockIdx.x >> 6;
    int m0 = mg * 64;

    // preload Wh slice (32 x 512 bf16, stride 520): 2048 uint4
    {
        const bf16* Wp = g_WhGt + (size_t)cu * CPC * UU;
        for (int i = tid; i < 2048; i += 256) {
            int n   = i >> 6;
            int seg = i & 63;
            *(uint4*)(Bs + n * 520 + seg * 8) = *(const uint4*)(Wp + n * UU + seg * 8);
        }
    }
    // preload Wx slice (32 x 256 bf16, stride 264): 1024 uint4
    {
        const bf16* Wp = g_WxGt + (size_t)cu * CPC * EE;
        for (int i = tid; i < 1024; i += 256) {
            int row = i >> 5;
            int seg = i & 31;
            *(uint4*)(Wxs + row * 264 + seg * 8) = *(const uint4*)(Wp + row * EE + seg * 8);
        }
    }

    // per-lane bias (kw2==0 warps only use it)
    float bi[4][2];
#pragma unroll
    for (int g = 0; g < 4; g++) {
        bi[g][0] = g_bG[cu * 32 + g * 8 + tg * 2];
        bi[g][1] = g_bG[cu * 32 + g * 8 + tg * 2 + 1];
    }

    // ldsm lane addresses (byte offsets), K-half shifted by kw2
    uint32_t aAddrH = hs_u32 + (uint32_t)((wm + (lane & 15)) * 1040 + kw2 * 512 + ((lane & 16) ? 16 : 0));
    uint32_t bH0 = Bs_u32 + (uint32_t)(((0  + (lane & 7) + ((lane & 16) ? 8 : 0)) * 520) * 2 + kw2 * 512 + ((lane & 8) ? 16 : 0));
    uint32_t bH1 = Bs_u32 + (uint32_t)(((16 + (lane & 7) + ((lane & 16) ? 8 : 0)) * 520) * 2 + kw2 * 512 + ((lane & 8) ? 16 : 0));
    uint32_t aAddrXbase = Es_u32 + (uint32_t)((wm + (lane & 15)) * 528 + kw2 * 256 + ((lane & 16) ? 16 : 0));
    uint32_t bX0 = Wxs_u32 + (uint32_t)(((0  + (lane & 7) + ((lane & 16) ? 8 : 0)) * 264) * 2 + kw2 * 256 + ((lane & 8) ? 16 : 0));
    uint32_t bX1 = Wxs_u32 + (uint32_t)(((16 + (lane & 7) + ((lane & 16) ? 8 : 0)) * 264) * 2 + kw2 * 256 + ((lane & 8) ? 16 : 0));

    // gate ownership (kw2==0): rows (m0+wm+gid, +8), units (cu*8 + tg*2, +1)
    int rowA = m0 + wm + gid;
    float c00 = 0.0f, c01 = 0.0f, c10 = 0.0f, c11 = 0.0f;

    unsigned* myflag   = g_flags + (size_t)(mg * 64 + cu) * 32;
    unsigned* pollflag = g_flags + (size_t)(mg * 64 + (tid & 63)) * 32;

    // ---- prologue: tokens(0) + own emb(0) quarter ----
    if (tid >= 64 && tid < 128) tks[tid - 64] = sentence[(m0 + tid - 64) * TT];
    __syncthreads();
    {
#pragma unroll
        for (int r = 0; r < 8; r++) {
            int i   = r * 32 + lane;
            int row = i >> 4;
            int seg = i & 15;
            int tok = tks[wm + row];
            cp_async16(Es_u32 + (uint32_t)((wm + row) * 528 + kw2 * 256 + seg * 16),
                       g_emb16 + (size_t)tok * EE + kw2 * 128 + seg * 8);
        }
        asm volatile("cp.async.commit_group;" ::: "memory");
    }

    float acc[4][4];

    for (int t = 0; t < TT; t++) {
        const bf16* hsrc = g_hbuf + (size_t)(t & 1) * (BB * UU);
        bf16*       hdst = g_hbuf + (size_t)((t + 1) & 1) * (BB * UU);

        // (a) own emb(t) ready
        asm volatile("cp.async.wait_group 0;" ::: "memory");
        __syncwarp();

        // (b) tokens(t+1) + (b') relaxed flag preload (hidden under x-GEMM)
        if (t + 1 < TT && tid >= 64 && tid < 128)
            tks[tid - 64] = sentence[(m0 + tid - 64) * TT + t + 1];
        unsigned fv = 0xffffffffu;
        if (tid < 64)
            asm volatile("ld.relaxed.gpu.u32 %0, [%1];" : "=r"(fv) : "l"(pollflag));

        // (c) x-GEMM over own K-half (8 iters)
#pragma unroll
        for (int g = 0; g < 4; g++) {
            if (kw2 == 0) {
                acc[g][0] = bi[g][0]; acc[g][1] = bi[g][1];
                acc[g][2] = bi[g][0]; acc[g][3] = bi[g][1];
            } else {
                acc[g][0] = 0.0f; acc[g][1] = 0.0f;
                acc[g][2] = 0.0f; acc[g][3] = 0.0f;
            }
        }
        {
            uint32_t aX = aAddrXbase + (uint32_t)((t & 1) * 33792);
#pragma unroll
            for (int kx = 0; kx < 8; kx++) {
                uint32_t kb = (uint32_t)(kx * 32);
                uint32_t a0, a1, a2, a3, b0, b1, b2, b3, b4, b5, b6, b7;
                ldsm_x4(a0, a1, a2, a3, aX + kb);
                ldsm_x4(b0, b1, b2, b3, bX0 + kb);
                ldsm_x4(b4, b5, b6, b7, bX1 + kb);
                mma_bf16(acc[0][0], acc[0][1], acc[0][2], acc[0][3], a0, a1, a2, a3, b0, b1);
                mma_bf16(acc[1][0], acc[1][1], acc[1][2], acc[1][3], a0, a1, a2, a3, b2, b3);
                mma_bf16(acc[2][0], acc[2][1], acc[2][2], acc[2][3], a0, a1, a2, a3, b4, b5);
                mma_bf16(acc[3][0], acc[3][1], acc[3][2], acc[3][3], a0, a1, a2, a3, b6, b7);
            }
        }

        // (d) finalize flag wait: fast path = fence; slow path = acquire spin
        if (tid < 64) {
            if (fv < (unsigned)t) {
                unsigned v;
                do {
                    asm volatile("ld.acquire.gpu.u32 %0, [%1];" : "=r"(v) : "l"(pollflag));
                } while (v < (unsigned)t);
            } else {
                asm volatile("fence.acq_rel.gpu;" ::: "memory");
            }
        }
        __syncthreads();   // S1

        // (e) stage OWN h data: 2 sub-chunks of 128 cols; then emb(t+1)
#pragma unroll
        for (int sub = 0; sub < 2; sub++) {
#pragma unroll
            for (int r = 0; r < 8; r++) {
                int i   = r * 32 + lane;
                int row = i >> 4;
                int seg = i & 15;
                cp_async16(hs_u32 + (uint32_t)(((wm + row) * 520 + kw2 * 256 + sub * 128 + seg * 8) * 2),
                           hsrc + (size_t)(m0 + wm + row) * UU + kw2 * 256 + sub * 128 + seg * 8);
            }
            asm volatile("cp.async.commit_group;" ::: "memory");
        }
        if (t + 1 < TT) {
            int p1 = (t + 1) & 1;
#pragma unroll
            for (int r = 0; r < 8; r++) {
                int i   = r * 32 + lane;
                int row = i >> 4;
                int seg = i & 15;
                int tok = tks[wm + row];
                cp_async16(Es_u32 + (uint32_t)(p1 * 33792 + (wm + row) * 528 + kw2 * 256 + seg * 16),
                           g_emb16 + (size_t)tok * EE + kw2 * 128 + seg * 8);
            }
        }
        asm volatile("cp.async.commit_group;" ::: "memory");   // emb group (maybe empty)

        // (f) h-GEMM over own K-half: 2 sub-chunks of 8 iters, per-warp pipelined
#define HSUB(SS, WG)                                                                \
        asm volatile("cp.async.wait_group " #WG ";" ::: "memory");                  \
        __syncwarp();                                                               \
        _Pragma("unroll")                                                           \
        for (int ks = (SS) * 8; ks < (SS) * 8 + 8; ks++) {                          \
            uint32_t kb = (uint32_t)(ks * 32);                                      \
            uint32_t a0, a1, a2, a3, b0, b1, b2, b3, b4, b5, b6, b7;                \
            ldsm_x4(a0, a1, a2, a3, aAddrH + kb);                                   \
            ldsm_x4(b0, b1, b2, b3, bH0 + kb);                                      \
            ldsm_x4(b4, b5, b6, b7, bH1 + kb);                                      \
            mma_bf16(acc[0][0], acc[0][1], acc[0][2], acc[0][3], a0, a1, a2, a3, b0, b1); \
            mma_bf16(acc[1][0], acc[1][1], acc[1][2], acc[1][3], a0, a1, a2, a3, b2, b3); \
            mma_bf16(acc[2][0], acc[2][1], acc[2][2], acc[2][3], a0, a1, a2, a3, b4, b5); \
            mma_bf16(acc[3][0], acc[3][1], acc[3][2], acc[3][3], a0, a1, a2, a3, b6, b7); \
        }

        HSUB(0, 2)
        HSUB(1, 1)
#undef HSUB

        // (g) K-reduction + gates
        if (kw2 == 1) {
#pragma unroll
            for (int g = 0; g < 4; g++)
#pragma unroll
                for (int q = 0; q < 4; q++)
                    sred[(wm + g * 4 + q) * 32 + lane] = acc[g][q];
        }
        __syncthreads();   // sync2: sred visible; also the rejoin point for kw2=1
        if (kw2 == 0) {
#pragma unroll
            for (int g = 0; g < 4; g++)
#pragma unroll
                for (int q = 0; q < 4; q++)
                    acc[g][q] += sred[(wm + g * 4 + q) * 32 + lane];

            float i0 = sigm_apx(acc[0][0]), fg0 = sigm_apx(acc[1][0]);
            float gg0 = tanh_apx(acc[2][0]), o0 = sigm_apx(acc[3][0]);
            c00 = fg0 * c00 + i0 * gg0;
            float h00 = o0 * tanh_apx(c00);

            float i1 = sigm_apx(acc[0][1]), fg1 = sigm_apx(acc[1][1]);
            float gg1 = tanh_apx(acc[2][1]), o1 = sigm_apx(acc[3][1]);
            c01 = fg1 * c01 + i1 * gg1;
            float h01 = o1 * tanh_apx(c01);

            float i2 = sigm_apx(acc[0][2]), fg2 = sigm_apx(acc[1][2]);
            float gg2 = tanh_apx(acc[2][2]), o2 = sigm_apx(acc[3][2]);
            c10 = fg2 * c10 + i2 * gg2;
            float h10 = o2 * tanh_apx(c10);

            float i3 = sigm_apx(acc[0][3]), fg3 = sigm_apx(acc[1][3]);
            float gg3 = tanh_apx(acc[2][3]), o3 = sigm_apx(acc[3][3]);
            c11 = fg3 * c11 + i3 * gg3;
            float h11 = o3 * tanh_apx(c11);

            __nv_bfloat162 hA, hB;
            hA.x = __float2bfloat16(h00); hA.y = __float2bfloat16(h01);
            hB.x = __float2bfloat16(h10); hB.y = __float2bfloat16(h11);
            size_t base = (size_t)rowA * UU + cu * UT + tg * 2;
            *(__nv_bfloat162*)(hdst + base)          = hA;
            *(__nv_bfloat162*)(hdst + base + 8 * UU) = hB;

            // (h) publish: barrier over the 4 h-store warps only; kw2=1 runs ahead
            asm volatile("bar.sync 1, 128;" ::: "memory");
            if (tid == 0) {
                asm volatile("st.release.gpu.u32 [%0], %1;" :: "l"(myflag), "r"(t + 1) : "memory");
            }
        }
    }
}

// ---------------- head: per-batch MLP (h(512) in buffer 0, plain layout) ----------------
__global__ __launch_bounds__(128) void k_head(const float* __restrict__ W1, const float* __restrict__ b1,
                                              const float* __restrict__ W2, const float* __restrict__ b2,
                                              const float* __restrict__ W3, const float* __restrict__ b3,
                                              float* __restrict__ out) {
    __shared__ float hsm[UU];
    __shared__ float h1[128];
    __shared__ float red[64];
    int b   = blockIdx.x;
    int tid = threadIdx.x;

    for (int i = tid; i < UU; i += 128)
        hsm[i] = __bfloat162float(g_hbuf[(size_t)b * UU + i]);
    __syncthreads();

    float a1 = b1[tid];
#pragma unroll 8
    for (int k = 0; k < UU; k++) a1 += hsm[k] * W1[k * 128 + tid];
    h1[tid] = fmaxf(a1, 0.0f);
    __syncthreads();

    if (tid < 64) {
        float a2 = b2[tid];
#pragma unroll 8
        for (int k = 0; k < 128; k++) a2 += h1[k] * W2[k * 64 + tid];
        a2 = fmaxf(a2, 0.0f);
        red[tid] = a2 * W3[tid];
    }
    __syncthreads();

    if (tid == 0) {
        float s = b3[0];
#pragma unroll 8
        for (int k = 0; k < 64; k++) s += red[k];
        out[b] = 1.0f / (1.0f + expf(-s));
    }
}

// ---------------- launch ----------------
extern "C" void kernel_launch(void* const* d_in, const int* in_sizes, int n_in,
                              void* d_out, int out_size) {
    const int*   sentence = (const int*)  d_in[0];
    const float* emb      = (const float*)d_in[1];
    const float* Wx       = (const float*)d_in[2];
    const float* Wh       = (const float*)d_in[3];
    const float* bvec     = (const float*)d_in[4];
    const float* W1       = (const float*)d_in[5];
    const float* b1       = (const float*)d_in[6];
    const float* W2       = (const float*)d_in[7];
    const float* b2       = (const float*)d_in[8];
    const float* W3       = (const float*)d_in[9];
    const float* b3       = (const float*)d_in[10];
    float* out = (float*)d_out;

    static bool attr_done = false;
    if (!attr_done) {
        cudaFuncSetAttribute(k_recur, cudaFuncAttributeMaxDynamicSharedMemorySize, 192768);
        attr_done = true;
    }

    k_cvt_emb<<<4096, 256>>>(emb);
    k_gather_wx<<<2048, 256>>>(Wx, bvec);
    k_gather_wh<<<4096, 256>>>(Wh);
    k_zero_state<<<256, 256>>>();

    k_recur<<<NCTA, 256, 192768>>>(sentence);

    k_head<<<128, 128>>>(W1, b1, W2, b2, W3, b3, out);
}

// round 17
// speedup vs baseline: 1.0571x; 1.0571x over previous
#include <cuda_runtime.h>
#include <cuda_bf16.h>
#include <cstdint>
#include <cstddef>

// Problem dims
#define BB   128
#define TT   512
#define EE   256
#define UU   512
#define ZZ   2048          // 4*U
#define NCU  64            // u-groups (8 units each)
#define UT   8             // units per CTA group
#define CPC  32            // z-cols per CTA (4 gates * 8 units)
#define NCTA 128           // persistent grid

typedef __nv_bfloat16 bf16;

// ---------------- scratch (device globals; no allocations) ----------------
__device__ __align__(16) bf16  g_emb16[32000 * EE];          // bf16 embedding (16.4 MB)
__device__ __align__(16) bf16  g_WxGt [NCU * CPC * EE];      // gathered Wx, [cu][jp][k] (1 MB)
__device__ __align__(16) bf16  g_WhGt [NCU * CPC * UU];      // gathered Wh, [cu][jp][k] (2 MB)
__device__ __align__(16) float g_bG   [ZZ];                  // gathered bias
__device__ __align__(1024) bf16 g_hbuf[2 * BB * UU];         // h double buffer
__device__ __align__(16) unsigned g_flags[NCTA * 32];        // per-CTA epoch flags, 128B padded

// gather map: gc -> original column
__device__ __forceinline__ int orig_col(int gc) {
    int cu   = gc >> 5;
    int gate = (gc >> 3) & 3;
    int j    = gc & 7;
    return gate * UU + cu * UT + j;
}

__device__ __forceinline__ float tanh_apx(float x) {
    float y;
    asm("tanh.approx.f32 %0, %1;" : "=f"(y) : "f"(x));
    return y;
}
__device__ __forceinline__ float sigm_apx(float x) {
    return fmaf(tanh_apx(0.5f * x), 0.5f, 0.5f);
}

__device__ __forceinline__ void mma_bf16(float& d0, float& d1, float& d2, float& d3,
                                         uint32_t a0, uint32_t a1, uint32_t a2, uint32_t a3,
                                         uint32_t b0, uint32_t b1) {
    asm volatile(
        "mma.sync.aligned.m16n8k16.row.col.f32.bf16.bf16.f32 "
        "{%0,%1,%2,%3}, {%4,%5,%6,%7}, {%8,%9}, {%0,%1,%2,%3};"
        : "+f"(d0), "+f"(d1), "+f"(d2), "+f"(d3)
        : "r"(a0), "r"(a1), "r"(a2), "r"(a3), "r"(b0), "r"(b1));
}

__device__ __forceinline__ void ldsm_x4(uint32_t& r0, uint32_t& r1, uint32_t& r2, uint32_t& r3,
                                        uint32_t addr) {
    asm volatile("ldmatrix.sync.aligned.m8n8.x4.shared.b16 {%0,%1,%2,%3}, [%4];"
                 : "=r"(r0), "=r"(r1), "=r"(r2), "=r"(r3) : "r"(addr));
}

__device__ __forceinline__ void cp_async16(uint32_t dst_smem, const void* src) {
    asm volatile("cp.async.cg.shared.global [%0], [%1], 16;" :: "r"(dst_smem), "l"(src));
}

// ---------------- init kernels ----------------
__global__ void k_cvt_emb(const float* __restrict__ src) {
    int n4 = 32000 * EE / 4;
    for (int i = blockIdx.x * blockDim.x + threadIdx.x; i < n4; i += gridDim.x * blockDim.x) {
        float4 v = *(const float4*)(src + (size_t)i * 4);
        bf16* d = g_emb16 + (size_t)i * 4;
        d[0] = __float2bfloat16(v.x);
        d[1] = __float2bfloat16(v.y);
        d[2] = __float2bfloat16(v.z);
        d[3] = __float2bfloat16(v.w);
    }
}

// gather Wx into [cu][jp][k] (32 rows x 256 K per u-group), like Wh
__global__ void k_gather_wx(const float* __restrict__ Wx, const float* __restrict__ bvec) {
    int n = NCU * CPC * EE;
    for (int i = blockIdx.x * blockDim.x + threadIdx.x; i < n; i += gridDim.x * blockDim.x) {
        int cu = i >> 13;             // / (32*256)
        int jp = (i >> 8) & 31;
        int k  = i & 255;
        int gate = jp >> 3;
        int j    = jp & 7;
        g_WxGt[i] = __float2bfloat16(Wx[(size_t)k * ZZ + gate * UU + cu * UT + j]);
    }
    int t = blockIdx.x * blockDim.x + threadIdx.x;
    if (t < ZZ) g_bG[t] = bvec[orig_col(t)];
}

__global__ void k_gather_wh(const float* __restrict__ Wh) {
    int n = NCU * CPC * UU;
    for (int i = blockIdx.x * blockDim.x + threadIdx.x; i < n; i += gridDim.x * blockDim.x) {
        int cu = i >> 14;             // / (32*512)
        int jp = (i >> 9) & 31;
        int k  = i & 511;
        int gate = jp >> 3;
        int j    = jp & 7;
        g_WhGt[i] = __float2bfloat16(Wh[(size_t)k * ZZ + gate * UU + cu * UT + j]);
    }
}

__global__ void k_zero_state() {
    int tid = blockIdx.x * blockDim.x + threadIdx.x;
    int n = BB * UU;
    for (int i = tid; i < n; i += gridDim.x * blockDim.x)
        g_hbuf[i] = __float2bfloat16(0.0f);     // buffer 0 (read by step 0)
    for (int i = tid; i < NCTA * 32; i += gridDim.x * blockDim.x)
        g_flags[i] = 0u;
}

// ---------------- fused persistent recurrence, 2-way K-split, private staging ----------------
// 128 CTAs x 256 threads (8 warps). cu = bx&63, mg = bx>>6.
// Warp (mw = warp&3, kw2 = warp>>2): A-rows [m0+16mw,+16), K-half [256*kw2,+256) of h,
// x K-half [128*kw2,+128). Private per-warp staging (own cp.async FIFO).
// R17: x-GEMM split 4+4 — first half hides the flag poll, second half fills the
// first-h-chunk cp.async latency window after staging issue.
// dyn smem layout (bytes):
//   Bs  (Wh 32x520)        @ 0       33280
//   hs  (h tile 64x520)    @ 33280   66560
//   Wxs (Wx 32x264)        @ 99840   16896
//   Es  (emb 2 x 64x264)   @ 116736  67584
//   sred(64 x 32 f32)      @ 184320  8192
//   tks (int 64)           @ 192512  256     -> total 192768
__global__ __launch_bounds__(256) void k_recur(const int* __restrict__ sentence) {
    extern __shared__ __align__(128) char dsm[];
    bf16*  Bs   = (bf16*)dsm;
    bf16*  Wxs  = (bf16*)(dsm + 99840);
    float* sred = (float*)(dsm + 184320);
    int*   tks  = (int*) (dsm + 192512);

    uint32_t base_u32 = (uint32_t)__cvta_generic_to_shared(dsm);
    uint32_t Bs_u32   = base_u32;
    uint32_t hs_u32   = base_u32 + 33280;
    uint32_t Wxs_u32  = base_u32 + 99840;
    uint32_t Es_u32   = base_u32 + 116736;

    int tid  = threadIdx.x;
    int warp = tid >> 5;
    int lane = tid & 31;
    int tg   = lane & 3;
    int gid  = lane >> 2;

    int mw  = warp & 3;
    int kw2 = warp >> 2;
    int wm  = mw * 16;

    int cu = blockIdx.x & 63;
    int mg = blockIdx.x >> 6;
    int m0 = mg * 64;

    // preload Wh slice (32 x 512 bf16, stride 520): 2048 uint4
    {
        const bf16* Wp = g_WhGt + (size_t)cu * CPC * UU;
        for (int i = tid; i < 2048; i += 256) {
            int n   = i >> 6;
            int seg = i & 63;
            *(uint4*)(Bs + n * 520 + seg * 8) = *(const uint4*)(Wp + n * UU + seg * 8);
        }
    }
    // preload Wx slice (32 x 256 bf16, stride 264): 1024 uint4
    {
        const bf16* Wp = g_WxGt + (size_t)cu * CPC * EE;
        for (int i = tid; i < 1024; i += 256) {
            int row = i >> 5;
            int seg = i & 31;
            *(uint4*)(Wxs + row * 264 + seg * 8) = *(const uint4*)(Wp + row * EE + seg * 8);
        }
    }

    // per-lane bias (kw2==0 warps only use it)
    float bi[4][2];
#pragma unroll
    for (int g = 0; g < 4; g++) {
        bi[g][0] = g_bG[cu * 32 + g * 8 + tg * 2];
        bi[g][1] = g_bG[cu * 32 + g * 8 + tg * 2 + 1];
    }

    // ldsm lane addresses (byte offsets), K-half shifted by kw2
    uint32_t aAddrH = hs_u32 + (uint32_t)((wm + (lane & 15)) * 1040 + kw2 * 512 + ((lane & 16) ? 16 : 0));
    uint32_t bH0 = Bs_u32 + (uint32_t)(((0  + (lane & 7) + ((lane & 16) ? 8 : 0)) * 520) * 2 + kw2 * 512 + ((lane & 8) ? 16 : 0));
    uint32_t bH1 = Bs_u32 + (uint32_t)(((16 + (lane & 7) + ((lane & 16) ? 8 : 0)) * 520) * 2 + kw2 * 512 + ((lane & 8) ? 16 : 0));
    uint32_t aAddrXbase = Es_u32 + (uint32_t)((wm + (lane & 15)) * 528 + kw2 * 256 + ((lane & 16) ? 16 : 0));
    uint32_t bX0 = Wxs_u32 + (uint32_t)(((0  + (lane & 7) + ((lane & 16) ? 8 : 0)) * 264) * 2 + kw2 * 256 + ((lane & 8) ? 16 : 0));
    uint32_t bX1 = Wxs_u32 + (uint32_t)(((16 + (lane & 7) + ((lane & 16) ? 8 : 0)) * 264) * 2 + kw2 * 256 + ((lane & 8) ? 16 : 0));

    // gate ownership (kw2==0): rows (m0+wm+gid, +8), units (cu*8 + tg*2, +1)
    int rowA = m0 + wm + gid;
    float c00 = 0.0f, c01 = 0.0f, c10 = 0.0f, c11 = 0.0f;

    unsigned* myflag   = g_flags + (size_t)(mg * 64 + cu) * 32;
    unsigned* pollflag = g_flags + (size_t)(mg * 64 + (tid & 63)) * 32;

    // ---- prologue: tokens(0) + own emb(0) quarter ----
    if (tid >= 64 && tid < 128) tks[tid - 64] = sentence[(m0 + tid - 64) * TT];
    __syncthreads();
    {
#pragma unroll
        for (int r = 0; r < 8; r++) {
            int i   = r * 32 + lane;
            int row = i >> 4;
            int seg = i & 15;
            int tok = tks[wm + row];
            cp_async16(Es_u32 + (uint32_t)((wm + row) * 528 + kw2 * 256 + seg * 16),
                       g_emb16 + (size_t)tok * EE + kw2 * 128 + seg * 8);
        }
        asm volatile("cp.async.commit_group;" ::: "memory");
    }

    float acc[4][4];

    for (int t = 0; t < TT; t++) {
        const bf16* hsrc = g_hbuf + (size_t)(t & 1) * (BB * UU);
        bf16*       hdst = g_hbuf + (size_t)((t + 1) & 1) * (BB * UU);

        // (a) own emb(t) ready
        asm volatile("cp.async.wait_group 0;" ::: "memory");
        __syncwarp();

        // (b) tokens(t+1)
        if (t + 1 < TT && tid >= 64 && tid < 128)
            tks[tid - 64] = sentence[(m0 + tid - 64) * TT + t + 1];

        // (c) x-GEMM first half (iters 0..3) — hides the flag poll below
#pragma unroll
        for (int g = 0; g < 4; g++) {
            if (kw2 == 0) {
                acc[g][0] = bi[g][0]; acc[g][1] = bi[g][1];
                acc[g][2] = bi[g][0]; acc[g][3] = bi[g][1];
            } else {
                acc[g][0] = 0.0f; acc[g][1] = 0.0f;
                acc[g][2] = 0.0f; acc[g][3] = 0.0f;
            }
        }
        uint32_t aX = aAddrXbase + (uint32_t)((t & 1) * 33792);

#define XSLICE(FROM, TO)                                                            \
        _Pragma("unroll")                                                           \
        for (int kx = (FROM); kx < (TO); kx++) {                                    \
            uint32_t kb = (uint32_t)(kx * 32);                                      \
            uint32_t a0, a1, a2, a3, b0, b1, b2, b3, b4, b5, b6, b7;                \
            ldsm_x4(a0, a1, a2, a3, aX + kb);                                       \
            ldsm_x4(b0, b1, b2, b3, bX0 + kb);                                      \
            ldsm_x4(b4, b5, b6, b7, bX1 + kb);                                      \
            mma_bf16(acc[0][0], acc[0][1], acc[0][2], acc[0][3], a0, a1, a2, a3, b0, b1); \
            mma_bf16(acc[1][0], acc[1][1], acc[1][2], acc[1][3], a0, a1, a2, a3, b2, b3); \
            mma_bf16(acc[2][0], acc[2][1], acc[2][2], acc[2][3], a0, a1, a2, a3, b4, b5); \
            mma_bf16(acc[3][0], acc[3][1], acc[3][2], acc[3][3], a0, a1, a2, a3, b6, b7); \
        }

        XSLICE(0, 4)

        // (d) poll flags >= t, then CTA sync (releases staging; tks visible)
        if (tid < 64) {
            unsigned v;
            do {
                asm volatile("ld.acquire.gpu.u32 %0, [%1];" : "=r"(v) : "l"(pollflag));
            } while (v < (unsigned)t);
        }
        __syncthreads();   // S1

        // (e) stage OWN h data: 2 sub-chunks of 128 cols; then emb(t+1)
#pragma unroll
        for (int sub = 0; sub < 2; sub++) {
#pragma unroll
            for (int r = 0; r < 8; r++) {
                int i   = r * 32 + lane;
                int row = i >> 4;
                int seg = i & 15;
                cp_async16(hs_u32 + (uint32_t)(((wm + row) * 520 + kw2 * 256 + sub * 128 + seg * 8) * 2),
                           hsrc + (size_t)(m0 + wm + row) * UU + kw2 * 256 + sub * 128 + seg * 8);
            }
            asm volatile("cp.async.commit_group;" ::: "memory");
        }
        if (t + 1 < TT) {
            int p1 = (t + 1) & 1;
#pragma unroll
            for (int r = 0; r < 8; r++) {
                int i   = r * 32 + lane;
                int row = i >> 4;
                int seg = i & 15;
                int tok = tks[wm + row];
                cp_async16(Es_u32 + (uint32_t)(p1 * 33792 + (wm + row) * 528 + kw2 * 256 + seg * 16),
                           g_emb16 + (size_t)tok * EE + kw2 * 128 + seg * 8);
            }
        }
        asm volatile("cp.async.commit_group;" ::: "memory");   // emb group (maybe empty)

        // (e') x-GEMM second half (iters 4..7) — fills the first-h-chunk latency window
        XSLICE(4, 8)
#undef XSLICE

        // (f) h-GEMM over own K-half: 2 sub-chunks of 8 iters, per-warp pipelined
#define HSUB(SS, WG)                                                                \
        asm volatile("cp.async.wait_group " #WG ";" ::: "memory");                  \
        __syncwarp();                                                               \
        _Pragma("unroll")                                                           \
        for (int ks = (SS) * 8; ks < (SS) * 8 + 8; ks++) {                          \
            uint32_t kb = (uint32_t)(ks * 32);                                      \
            uint32_t a0, a1, a2, a3, b0, b1, b2, b3, b4, b5, b6, b7;                \
            ldsm_x4(a0, a1, a2, a3, aAddrH + kb);                                   \
            ldsm_x4(b0, b1, b2, b3, bH0 + kb);                                      \
            ldsm_x4(b4, b5, b6, b7, bH1 + kb);                                      \
            mma_bf16(acc[0][0], acc[0][1], acc[0][2], acc[0][3], a0, a1, a2, a3, b0, b1); \
            mma_bf16(acc[1][0], acc[1][1], acc[1][2], acc[1][3], a0, a1, a2, a3, b2, b3); \
            mma_bf16(acc[2][0], acc[2][1], acc[2][2], acc[2][3], a0, a1, a2, a3, b4, b5); \
            mma_bf16(acc[3][0], acc[3][1], acc[3][2], acc[3][3], a0, a1, a2, a3, b6, b7); \
        }

        HSUB(0, 2)
        HSUB(1, 1)
#undef HSUB

        // (g) K-reduction + gates
        if (kw2 == 1) {
#pragma unroll
            for (int g = 0; g < 4; g++)
#pragma unroll
                for (int q = 0; q < 4; q++)
                    sred[(wm + g * 4 + q) * 32 + lane] = acc[g][q];
        }
        __syncthreads();   // sync2
        if (kw2 == 0) {
#pragma unroll
            for (int g = 0; g < 4; g++)
#pragma unroll
                for (int q = 0; q < 4; q++)
                    acc[g][q] += sred[(wm + g * 4 + q) * 32 + lane];

            float i0 = sigm_apx(acc[0][0]), fg0 = sigm_apx(acc[1][0]);
            float gg0 = tanh_apx(acc[2][0]), o0 = sigm_apx(acc[3][0]);
            c00 = fg0 * c00 + i0 * gg0;
            float h00 = o0 * tanh_apx(c00);

            float i1 = sigm_apx(acc[0][1]), fg1 = sigm_apx(acc[1][1]);
            float gg1 = tanh_apx(acc[2][1]), o1 = sigm_apx(acc[3][1]);
            c01 = fg1 * c01 + i1 * gg1;
            float h01 = o1 * tanh_apx(c01);

            float i2 = sigm_apx(acc[0][2]), fg2 = sigm_apx(acc[1][2]);
            float gg2 = tanh_apx(acc[2][2]), o2 = sigm_apx(acc[3][2]);
            c10 = fg2 * c10 + i2 * gg2;
            float h10 = o2 * tanh_apx(c10);

            float i3 = sigm_apx(acc[0][3]), fg3 = sigm_apx(acc[1][3]);
            float gg3 = tanh_apx(acc[2][3]), o3 = sigm_apx(acc[3][3]);
            c11 = fg3 * c11 + i3 * gg3;
            float h11 = o3 * tanh_apx(c11);

            __nv_bfloat162 hA, hB;
            hA.x = __float2bfloat16(h00); hA.y = __float2bfloat16(h01);
            hB.x = __float2bfloat16(h10); hB.y = __float2bfloat16(h11);
            size_t base = (size_t)rowA * UU + cu * UT + tg * 2;
            *(__nv_bfloat162*)(hdst + base)          = hA;
            *(__nv_bfloat162*)(hdst + base + 8 * UU) = hB;
        }

        // (h) publish
        __syncthreads();
        if (tid == 0) {
            asm volatile("st.release.gpu.u32 [%0], %1;" :: "l"(myflag), "r"(t + 1) : "memory");
        }
    }
}

// ---------------- head: per-batch MLP (h(512) in buffer 0, plain layout) ----------------
__global__ __launch_bounds__(128) void k_head(const float* __restrict__ W1, const float* __restrict__ b1,
                                              const float* __restrict__ W2, const float* __restrict__ b2,
                                              const float* __restrict__ W3, const float* __restrict__ b3,
                                              float* __restrict__ out) {
    __shared__ float hsm[UU];
    __shared__ float h1[128];
    __shared__ float red[64];
    int b   = blockIdx.x;
    int tid = threadIdx.x;

    for (int i = tid; i < UU; i += 128)
        hsm[i] = __bfloat162float(g_hbuf[(size_t)b * UU + i]);
    __syncthreads();

    float a1 = b1[tid];
#pragma unroll 8
    for (int k = 0; k < UU; k++) a1 += hsm[k] * W1[k * 128 + tid];
    h1[tid] = fmaxf(a1, 0.0f);
    __syncthreads();

    if (tid < 64) {
        float a2 = b2[tid];
#pragma unroll 8
        for (int k = 0; k < 128; k++) a2 += h1[k] * W2[k * 64 + tid];
        a2 = fmaxf(a2, 0.0f);
        red[tid] = a2 * W3[tid];
    }
    __syncthreads();

    if (tid == 0) {
        float s = b3[0];
#pragma unroll 8
        for (int k = 0; k < 64; k++) s += red[k];
        out[b] = 1.0f / (1.0f + expf(-s));
    }
}

// ---------------- launch ----------------
extern "C" void kernel_launch(void* const* d_in, const int* in_sizes, int n_in,
                              void* d_out, int out_size) {
    const int*   sentence = (const int*)  d_in[0];
    const float* emb      = (const float*)d_in[1];
    const float* Wx       = (const float*)d_in[2];
    const float* Wh       = (const float*)d_in[3];
    const float* bvec     = (const float*)d_in[4];
    const float* W1       = (const float*)d_in[5];
    const float* b1       = (const float*)d_in[6];
    const float* W2       = (const float*)d_in[7];
    const float* b2       = (const float*)d_in[8];
    const float* W3       = (const float*)d_in[9];
    const float* b3       = (const float*)d_in[10];
    float* out = (float*)d_out;

    static bool attr_done = false;
    if (!attr_done) {
        cudaFuncSetAttribute(k_recur, cudaFuncAttributeMaxDynamicSharedMemorySize, 192768);
        attr_done = true;
    }

    k_cvt_emb<<<4096, 256>>>(emb);
    k_gather_wx<<<2048, 256>>>(Wx, bvec);
    k_gather_wh<<<4096, 256>>>(Wh);
    k_zero_state<<<256, 256>>>();

    k_recur<<<NCTA, 256, 192768>>>(sentence);

    k_head<<<128, 128>>>(W1, b1, W2, b2, W3, b3, out);
}